// round 7
// baseline (speedup 1.0000x reference)
#include <cuda_runtime.h>
#include <cstdint>
#include <cstddef>

#define NN 100000
#define EE 1600000
#define HD 128
#define CAP 64

typedef unsigned long long ull;

// ---- scratch (__device__ globals; allocations forbidden) ----
__device__ float g_h[(size_t)NN * HD];
__device__ float g_agg[(size_t)NN * HD];
__device__ float g_hw[(size_t)NN * HD];          // rare-path GEMM operand
__device__ int   g_cnt[NN];
__device__ int   g_col[(size_t)NN * CAP];
__device__ int   g_spill_cnt;
__device__ int2  g_spill[EE];
// k-major transposed weights (built once per launch)
__device__ __align__(16) float g_WinT[128 * 128];
__device__ __align__(16) float g_WdT[2 * 256 * 128];
__device__ __align__(16) float g_WihT[3 * 128 * 128];
__device__ __align__(16) float g_WhhT[3 * 128 * 128];

__device__ __forceinline__ float sigmoidf_(float x) { return 1.0f / (1.0f + expf(-x)); }
__device__ __forceinline__ float softplusf_(float x) {
    return fmaxf(x, 0.0f) + log1pf(expf(-fabsf(x)));
}

// ---- packed f32x2 helpers (FFMA2 only reachable via PTX) ----
__device__ __forceinline__ ull splat2(float x) {
    ull r; asm("mov.b64 %0, {%1, %1};" : "=l"(r) : "f"(x)); return r;
}
__device__ __forceinline__ ull pack2(float lo, float hi) {
    ull r; asm("mov.b64 %0, {%1, %2};" : "=l"(r) : "f"(lo), "f"(hi)); return r;
}
__device__ __forceinline__ void unpack2(float& lo, float& hi, ull v) {
    asm("mov.b64 {%0, %1}, %2;" : "=f"(lo), "=f"(hi) : "l"(v));
}
__device__ __forceinline__ void fma2(ull& d, ull a, ull b) {
    asm("fma.rn.f32x2 %0, %1, %2, %3;" : "=l"(d) : "l"(a), "l"(b), "l"(d));
}

// ---------------------------------------------------------------------------
// Packed 32-k micro-tile, k-major weights straight from global:
//   acc[8 nodes][2 f32x2 pairs] += A[i0..+7][aofs..+31] * WT(k-major, ld=128)
// ---------------------------------------------------------------------------
__device__ __forceinline__ void mma8g(ull acc[8][2], const float* __restrict__ WT,
                                      const float* __restrict__ A, int lda, int aofs,
                                      int i0, int j0) {
#pragma unroll
    for (int k4 = 0; k4 < 8; ++k4) {
        ull w[4][2];
#pragma unroll
        for (int t = 0; t < 4; ++t) {
            const ulonglong2 wv = *reinterpret_cast<const ulonglong2*>(
                WT + (k4 * 4 + t) * 128 + j0);
            w[t][0] = wv.x; w[t][1] = wv.y;
        }
#pragma unroll
        for (int u = 0; u < 8; ++u) {
            const float4 av = *reinterpret_cast<const float4*>(
                A + (size_t)(i0 + u) * lda + aofs + k4 * 4);
            ull s;
            s = splat2(av.x); fma2(acc[u][0], s, w[0][0]); fma2(acc[u][1], s, w[0][1]);
            s = splat2(av.y); fma2(acc[u][0], s, w[1][0]); fma2(acc[u][1], s, w[1][1]);
            s = splat2(av.z); fma2(acc[u][0], s, w[2][0]); fma2(acc[u][1], s, w[2][1]);
            s = splat2(av.w); fma2(acc[u][0], s, w[3][0]); fma2(acc[u][1], s, w[3][1]);
        }
    }
}

// ---------------------------------------------------------------------------
// prep: all weight transposes + cnt/spill zero, one kernel.
//   [0,16384)        W_in  -> g_WinT
//   [16384,81920)    Wd    -> g_WdT
//   [81920,131072)   Wih   -> g_WihT
//   [131072,180224)  Whh   -> g_WhhT
//   [180224,280224)  g_cnt = 0 ; idx==280224 -> g_spill_cnt = 0
// ---------------------------------------------------------------------------
__global__ __launch_bounds__(256) void prep_kernel(const float* __restrict__ W_in,
                                                   const float* __restrict__ Wd,
                                                   const float* __restrict__ Wih,
                                                   const float* __restrict__ Whh) {
    const int idx = blockIdx.x * 256 + threadIdx.x;
    if (idx < 16384) {
        const int j = idx >> 7, k = idx & 127;
        g_WinT[k * 128 + j] = W_in[idx];
    } else if (idx < 81920) {
        const int e = idx - 16384;
        const int l = e >> 15, rem = e & 32767;
        const int j = rem >> 8, k = rem & 255;
        g_WdT[l * 32768 + k * 128 + j] = Wd[e];
    } else if (idx < 131072) {
        const int e = idx - 81920;
        const int j = e >> 7, k = e & 127;
        const int g = j >> 7, jj = j & 127;
        g_WihT[g * 16384 + k * 128 + jj] = Wih[e];
    } else if (idx < 180224) {
        const int e = idx - 131072;
        const int j = e >> 7, k = e & 127;
        const int g = j >> 7, jj = j & 127;
        g_WhhT[g * 16384 + k * 128 + jj] = Whh[e];
    } else if (idx < 280224) {
        g_cnt[idx - 180224] = 0;
    } else if (idx == 280224) {
        g_spill_cnt = 0;
    }
}

// ---------------------------------------------------------------------------
// h0 = relu(x @ W_in^T + b_in)
// ---------------------------------------------------------------------------
__global__ __launch_bounds__(128, 6) void in_gemm_kernel(const float* __restrict__ x,
                                                         const float* __restrict__ b) {
    const int node0 = blockIdx.x * 32;
    const int lane = threadIdx.x & 31;
    const int i0 = (threadIdx.x >> 5) * 8, j0 = lane * 4;
    const float* A = x + (size_t)node0 * HD;

    ull acc[8][2];
    {
        const float4 b4 = *reinterpret_cast<const float4*>(b + j0);
        const ull b0 = pack2(b4.x, b4.y), b1 = pack2(b4.z, b4.w);
#pragma unroll
        for (int u = 0; u < 8; ++u) { acc[u][0] = b0; acc[u][1] = b1; }
    }
#pragma unroll 1
    for (int kt = 0; kt < 4; ++kt)
        mma8g(acc, g_WinT + kt * 4096, A, HD, kt * 32, i0, j0);

#pragma unroll
    for (int u = 0; u < 8; ++u) {
        float a0, a1, a2, a3;
        unpack2(a0, a1, acc[u][0]);
        unpack2(a2, a3, acc[u][1]);
        *reinterpret_cast<float4*>(g_h + (size_t)(node0 + i0 + u) * HD + j0) =
            make_float4(fmaxf(a0, 0.f), fmaxf(a1, 0.f), fmaxf(a2, 0.f), fmaxf(a3, 0.f));
    }
}

// ---------------------------------------------------------------------------
// Edge structure: capacity-slot scatter (exact; overflow -> spill list)
// ---------------------------------------------------------------------------
__global__ __launch_bounds__(256) void scatter_kernel(const int* __restrict__ ei) {
    const int idx = blockIdx.x * 256 + threadIdx.x;  // 2 edges/thread
    const int2 r = reinterpret_cast<const int2*>(ei)[idx];
    const int2 c = reinterpret_cast<const int2*>(ei + EE)[idx];
    int pos = atomicAdd(&g_cnt[r.x], 1);
    if (pos < CAP) g_col[(size_t)r.x * CAP + pos] = c.x;
    else { int s = atomicAdd(&g_spill_cnt, 1); g_spill[s] = make_int2(r.x, c.x); }
    pos = atomicAdd(&g_cnt[r.y], 1);
    if (pos < CAP) g_col[(size_t)r.y * CAP + pos] = c.y;
    else { int s = atomicAdd(&g_spill_cnt, 1); g_spill[s] = make_int2(r.y, c.y); }
}

// ---------------------------------------------------------------------------
// agg[n] = sum_{neighbors} |h[n] - h[c]|   (warp/node, MLP=8 gather)
// ---------------------------------------------------------------------------
__global__ __launch_bounds__(512) void agg_kernel() {
    const int node = blockIdx.x * 16 + (threadIdx.x >> 5);
    const int lane = threadIdx.x & 31;
    const float* __restrict__ h = g_h;
    const float4 hi = *reinterpret_cast<const float4*>(h + (size_t)node * HD + lane * 4);
    float4 acc = make_float4(0.f, 0.f, 0.f, 0.f);
    const int deg = min(g_cnt[node], CAP);
    const int* base = g_col + (size_t)node * CAP;
    int e = 0;
    for (; e + 8 <= deg; e += 8) {
        const int4 ia = *reinterpret_cast<const int4*>(base + e);
        const int4 ib = *reinterpret_cast<const int4*>(base + e + 4);
        const float4 v0 = *reinterpret_cast<const float4*>(h + (size_t)ia.x * HD + lane * 4);
        const float4 v1 = *reinterpret_cast<const float4*>(h + (size_t)ia.y * HD + lane * 4);
        const float4 v2 = *reinterpret_cast<const float4*>(h + (size_t)ia.z * HD + lane * 4);
        const float4 v3 = *reinterpret_cast<const float4*>(h + (size_t)ia.w * HD + lane * 4);
        const float4 v4 = *reinterpret_cast<const float4*>(h + (size_t)ib.x * HD + lane * 4);
        const float4 v5 = *reinterpret_cast<const float4*>(h + (size_t)ib.y * HD + lane * 4);
        const float4 v6 = *reinterpret_cast<const float4*>(h + (size_t)ib.z * HD + lane * 4);
        const float4 v7 = *reinterpret_cast<const float4*>(h + (size_t)ib.w * HD + lane * 4);
        acc.x += fabsf(hi.x - v0.x) + fabsf(hi.x - v1.x) + fabsf(hi.x - v2.x) + fabsf(hi.x - v3.x)
               + fabsf(hi.x - v4.x) + fabsf(hi.x - v5.x) + fabsf(hi.x - v6.x) + fabsf(hi.x - v7.x);
        acc.y += fabsf(hi.y - v0.y) + fabsf(hi.y - v1.y) + fabsf(hi.y - v2.y) + fabsf(hi.y - v3.y)
               + fabsf(hi.y - v4.y) + fabsf(hi.y - v5.y) + fabsf(hi.y - v6.y) + fabsf(hi.y - v7.y);
        acc.z += fabsf(hi.z - v0.z) + fabsf(hi.z - v1.z) + fabsf(hi.z - v2.z) + fabsf(hi.z - v3.z)
               + fabsf(hi.z - v4.z) + fabsf(hi.z - v5.z) + fabsf(hi.z - v6.z) + fabsf(hi.z - v7.z);
        acc.w += fabsf(hi.w - v0.w) + fabsf(hi.w - v1.w) + fabsf(hi.w - v2.w) + fabsf(hi.w - v3.w)
               + fabsf(hi.w - v4.w) + fabsf(hi.w - v5.w) + fabsf(hi.w - v6.w) + fabsf(hi.w - v7.w);
    }
    for (; e < deg; ++e) {
        const int c0 = base[e];
        const float4 a = *reinterpret_cast<const float4*>(h + (size_t)c0 * HD + lane * 4);
        acc.x += fabsf(hi.x - a.x);
        acc.y += fabsf(hi.y - a.y);
        acc.z += fabsf(hi.z - a.z);
        acc.w += fabsf(hi.w - a.w);
    }
    *reinterpret_cast<float4*>(g_agg + (size_t)node * HD + lane * 4) = acc;
}

// Exact fix-up for capacity overflow (normally zero work)
__global__ __launch_bounds__(256) void spill_kernel() {
    const int gw = blockIdx.x * 8 + (threadIdx.x >> 5);
    const int lane = threadIdx.x & 31;
    const int n = g_spill_cnt;
    for (int s = gw; s < n; s += 64) {
        const int2 e = g_spill[s];
        const float4 a = *reinterpret_cast<const float4*>(g_h + (size_t)e.x * HD + lane * 4);
        const float4 b = *reinterpret_cast<const float4*>(g_h + (size_t)e.y * HD + lane * 4);
        float* p = g_agg + (size_t)e.x * HD + lane * 4;
        asm volatile("red.global.add.v4.f32 [%0], {%1,%2,%3,%4};"
                     :: "l"(p), "f"(fabsf(a.x - b.x)), "f"(fabsf(a.y - b.y)),
                        "f"(fabsf(a.z - b.z)), "f"(fabsf(a.w - b.w)) : "memory");
    }
}

// ---------------------------------------------------------------------------
// Fused node kernel. hw lives in thread-private smem (each thread re-reads
// only the 16B it wrote -> zero syncs). tau partial fused into unpack loop.
// Per-warp GRU skip; exact per-warp fallback via g_hw.
// Layer 2 (out != null): fused output GEMV, h never stored.
// ---------------------------------------------------------------------------
__global__ __launch_bounds__(128, 5) void node_kernel(
    int layer, const float* __restrict__ bd,
    const float* __restrict__ Wt, const float* __restrict__ bt,
    const float* __restrict__ bih, const float* __restrict__ bhh,
    const float* __restrict__ Wo, const float* __restrict__ bo,
    float* __restrict__ out, float* __restrict__ tau_out) {
    __shared__ float HWs[32 * 128];   // 16 KB
    const int node0 = blockIdx.x * 32;
    const int lane = threadIdx.x & 31;
    const int i0 = (threadIdx.x >> 5) * 8, j0 = lane * 4;
    const float* WdTl = g_WdT + layer * 32768;
    const float* Ah = g_h + (size_t)node0 * HD;
    const float* Aa = g_agg + (size_t)node0 * HD;

    // ---- phase 1: hw = relu([h,agg] @ Wd^T + bd), tau partial fused ----
    ull acc[8][2];
    {
        const float4 b4 = *reinterpret_cast<const float4*>(bd + j0);
        const ull b0 = pack2(b4.x, b4.y), b1 = pack2(b4.z, b4.w);
#pragma unroll
        for (int u = 0; u < 8; ++u) { acc[u][0] = b0; acc[u][1] = b1; }
    }
#pragma unroll 1
    for (int kt = 0; kt < 4; ++kt)
        mma8g(acc, WdTl + kt * 4096, Ah, HD, kt * 32, i0, j0);
#pragma unroll 1
    for (int kt = 0; kt < 4; ++kt)
        mma8g(acc, WdTl + 16384 + kt * 4096, Aa, HD, kt * 32, i0, j0);

    const float4 wt4 = *reinterpret_cast<const float4*>(Wt + j0);
    float p[8];
#pragma unroll
    for (int u = 0; u < 8; ++u) {
        float a0, a1, a2, a3;
        unpack2(a0, a1, acc[u][0]);
        unpack2(a2, a3, acc[u][1]);
        a0 = fmaxf(a0, 0.f); a1 = fmaxf(a1, 0.f);
        a2 = fmaxf(a2, 0.f); a3 = fmaxf(a3, 0.f);
        *reinterpret_cast<float4*>(HWs + (i0 + u) * 128 + j0) =
            make_float4(a0, a1, a2, a3);
        p[u] = a0 * wt4.x + a1 * wt4.y + a2 * wt4.z + a3 * wt4.w;
    }

    // ---- phase 2: tau = softplus(sum + bt) (uniform across warp) ----
    const float bt0 = bt[0];
    int mskbits = 0;
#pragma unroll
    for (int u = 0; u < 8; ++u) {
        float s = p[u];
#pragma unroll
        for (int o = 16; o > 0; o >>= 1) s += __shfl_xor_sync(0xffffffffu, s, o);
        s = __shfl_sync(0xffffffffu, s, 0);
        const float tv = softplusf_(s + bt0);
        if (tau_out && lane == 0) tau_out[node0 + i0 + u] = tv;
        if (tv < 0.005f) mskbits |= 1 << u;
    }
    const bool rare = __any_sync(0xffffffffu, mskbits != 0);

    if (!rare) {
        if (out) {
            const float4 wo0 = *reinterpret_cast<const float4*>(Wo + j0);
            const float4 wo1 = *reinterpret_cast<const float4*>(Wo + 128 + j0);
            const float bo0 = bo[0], bo1 = bo[1];
#pragma unroll
            for (int u = 0; u < 8; ++u) {
                const float4 hw4 = *reinterpret_cast<const float4*>(HWs + (i0 + u) * 128 + j0);
                float p0 = hw4.x * wo0.x + hw4.y * wo0.y + hw4.z * wo0.z + hw4.w * wo0.w;
                float p1 = hw4.x * wo1.x + hw4.y * wo1.y + hw4.z * wo1.z + hw4.w * wo1.w;
#pragma unroll
                for (int o = 16; o > 0; o >>= 1) {
                    p0 += __shfl_xor_sync(0xffffffffu, p0, o);
                    p1 += __shfl_xor_sync(0xffffffffu, p1, o);
                }
                if (lane == 0)
                    *reinterpret_cast<float2*>(out + (size_t)(node0 + i0 + u) * 2) =
                        make_float2(p0 + bo0, p1 + bo1);
            }
        } else {
#pragma unroll
            for (int u = 0; u < 8; ++u)
                *reinterpret_cast<float4*>(g_h + (size_t)(node0 + i0 + u) * HD + j0) =
                    *reinterpret_cast<const float4*>(HWs + (i0 + u) * 128 + j0);
        }
        return;
    }

    // ---- rare path: exact per-warp masked GRU(agg, hw) ----
    const float* Ahw = g_hw + (size_t)node0 * HD;
#pragma unroll
    for (int u = 0; u < 8; ++u)
        *reinterpret_cast<float4*>(g_hw + (size_t)(node0 + i0 + u) * HD + j0) =
            *reinterpret_cast<const float4*>(HWs + (i0 + u) * 128 + j0);
    __threadfence_block();
    __syncwarp();

    // r gate
    float r_[8][4];
    {
        ull ga[8][2];
        const float4 bi = *reinterpret_cast<const float4*>(bih + j0);
        const float4 bh = *reinterpret_cast<const float4*>(bhh + j0);
        const ull b0 = pack2(bi.x + bh.x, bi.y + bh.y);
        const ull b1 = pack2(bi.z + bh.z, bi.w + bh.w);
#pragma unroll
        for (int u = 0; u < 8; ++u) { ga[u][0] = b0; ga[u][1] = b1; }
#pragma unroll 1
        for (int kt = 0; kt < 4; ++kt)
            mma8g(ga, g_WihT + kt * 4096, Aa, HD, kt * 32, i0, j0);
#pragma unroll 1
        for (int kt = 0; kt < 4; ++kt)
            mma8g(ga, g_WhhT + kt * 4096, Ahw, HD, kt * 32, i0, j0);
#pragma unroll
        for (int u = 0; u < 8; ++u) {
            float a0, a1, a2, a3;
            unpack2(a0, a1, ga[u][0]); unpack2(a2, a3, ga[u][1]);
            r_[u][0] = sigmoidf_(a0); r_[u][1] = sigmoidf_(a1);
            r_[u][2] = sigmoidf_(a2); r_[u][3] = sigmoidf_(a3);
        }
    }
    // rh = r * (bhh_n + hw@Whhn^T)
    float rh[8][4];
    {
        ull hn[8][2];
        const float4 bh = *reinterpret_cast<const float4*>(bhh + 256 + j0);
        const ull b0 = pack2(bh.x, bh.y), b1 = pack2(bh.z, bh.w);
#pragma unroll
        for (int u = 0; u < 8; ++u) { hn[u][0] = b0; hn[u][1] = b1; }
#pragma unroll 1
        for (int kt = 0; kt < 4; ++kt)
            mma8g(hn, g_WhhT + 32768 + kt * 4096, Ahw, HD, kt * 32, i0, j0);
#pragma unroll
        for (int u = 0; u < 8; ++u) {
            float a0, a1, a2, a3;
            unpack2(a0, a1, hn[u][0]); unpack2(a2, a3, hn[u][1]);
            rh[u][0] = r_[u][0] * a0; rh[u][1] = r_[u][1] * a1;
            rh[u][2] = r_[u][2] * a2; rh[u][3] = r_[u][3] * a3;
        }
    }
    // n = tanh(bih_n + agg@Wihn^T + rh)
    float n_[8][4];
    {
        ull in_[8][2];
        const float4 bi = *reinterpret_cast<const float4*>(bih + 256 + j0);
        const ull b0 = pack2(bi.x, bi.y), b1 = pack2(bi.z, bi.w);
#pragma unroll
        for (int u = 0; u < 8; ++u) { in_[u][0] = b0; in_[u][1] = b1; }
#pragma unroll 1
        for (int kt = 0; kt < 4; ++kt)
            mma8g(in_, g_WihT + 32768 + kt * 4096, Aa, HD, kt * 32, i0, j0);
#pragma unroll
        for (int u = 0; u < 8; ++u) {
            float a0, a1, a2, a3;
            unpack2(a0, a1, in_[u][0]); unpack2(a2, a3, in_[u][1]);
            n_[u][0] = tanhf(a0 + rh[u][0]); n_[u][1] = tanhf(a1 + rh[u][1]);
            n_[u][2] = tanhf(a2 + rh[u][2]); n_[u][3] = tanhf(a3 + rh[u][3]);
        }
    }
    // z gate + combine + output
    {
        ull gz[8][2];
        const float4 bi = *reinterpret_cast<const float4*>(bih + 128 + j0);
        const float4 bh = *reinterpret_cast<const float4*>(bhh + 128 + j0);
        const ull b0 = pack2(bi.x + bh.x, bi.y + bh.y);
        const ull b1 = pack2(bi.z + bh.z, bi.w + bh.w);
#pragma unroll
        for (int u = 0; u < 8; ++u) { gz[u][0] = b0; gz[u][1] = b1; }
#pragma unroll 1
        for (int kt = 0; kt < 4; ++kt)
            mma8g(gz, g_WihT + 16384 + kt * 4096, Aa, HD, kt * 32, i0, j0);
#pragma unroll 1
        for (int kt = 0; kt < 4; ++kt)
            mma8g(gz, g_WhhT + 16384 + kt * 4096, Ahw, HD, kt * 32, i0, j0);

        const float4 wo0 = out ? *reinterpret_cast<const float4*>(Wo + j0) : make_float4(0,0,0,0);
        const float4 wo1 = out ? *reinterpret_cast<const float4*>(Wo + 128 + j0) : make_float4(0,0,0,0);
        const float bo0 = out ? bo[0] : 0.f, bo1 = out ? bo[1] : 0.f;
#pragma unroll
        for (int u = 0; u < 8; ++u) {
            float a0, a1, a2, a3;
            unpack2(a0, a1, gz[u][0]); unpack2(a2, a3, gz[u][1]);
            const float zv[4] = {sigmoidf_(a0), sigmoidf_(a1), sigmoidf_(a2), sigmoidf_(a3)};
            const float4 hw4 = *reinterpret_cast<const float4*>(HWs + (i0 + u) * 128 + j0);
            const float hwv[4] = {hw4.x, hw4.y, hw4.z, hw4.w};
            const bool msk = (mskbits >> u) & 1;
            float ov[4];
#pragma unroll
            for (int v = 0; v < 4; ++v) {
                const float hn = (1.0f - zv[v]) * n_[u][v] + zv[v] * hwv[v];
                ov[v] = msk ? hn : hwv[v];
            }
            if (out) {
                float p0 = ov[0] * wo0.x + ov[1] * wo0.y + ov[2] * wo0.z + ov[3] * wo0.w;
                float p1 = ov[0] * wo1.x + ov[1] * wo1.y + ov[2] * wo1.z + ov[3] * wo1.w;
#pragma unroll
                for (int o = 16; o > 0; o >>= 1) {
                    p0 += __shfl_xor_sync(0xffffffffu, p0, o);
                    p1 += __shfl_xor_sync(0xffffffffu, p1, o);
                }
                if (lane == 0)
                    *reinterpret_cast<float2*>(out + (size_t)(node0 + i0 + u) * 2) =
                        make_float2(p0 + bo0, p1 + bo1);
            } else {
                *reinterpret_cast<float4*>(g_h + (size_t)(node0 + i0 + u) * HD + j0) =
                    make_float4(ov[0], ov[1], ov[2], ov[3]);
            }
        }
    }
}

// ---------------------------------------------------------------------------
extern "C" void kernel_launch(void* const* d_in, const int* in_sizes, int n_in,
                              void* d_out, int out_size) {
    const float* x    = (const float*)d_in[0];
    const int*   ei   = (const int*)d_in[1];   // int32 (JAX x64-disabled)
    const float* W_in = (const float*)d_in[2];
    const float* b_in = (const float*)d_in[3];
    const float* Wd   = (const float*)d_in[4];
    const float* bd   = (const float*)d_in[5];
    const float* Wt   = (const float*)d_in[6];
    const float* bt   = (const float*)d_in[7];
    const float* Wih  = (const float*)d_in[8];
    const float* Whh  = (const float*)d_in[9];
    const float* bih  = (const float*)d_in[10];
    const float* bhh  = (const float*)d_in[11];
    const float* Wo   = (const float*)d_in[12];
    const float* bo   = (const float*)d_in[13];

    float* out = (float*)d_out;
    float* tau_out = (out_size >= NN * 3) ? out + (size_t)NN * 2 : nullptr;

    prep_kernel<<<(280225 + 255) / 256, 256>>>(W_in, Wd, Wih, Whh);
    scatter_kernel<<<EE / 512, 256>>>(ei);
    in_gemm_kernel<<<NN / 32, 128>>>(x, b_in);

    for (int l = 0; l < 2; ++l) {
        agg_kernel<<<NN / 16, 512>>>();
        spill_kernel<<<8, 256>>>();
        node_kernel<<<NN / 32, 128>>>(
            l, bd + (size_t)l * HD, Wt, bt, bih, bhh, Wo, bo,
            (l == 1) ? out : nullptr, (l == 1) ? tau_out : nullptr);
    }
}

// round 9
// speedup vs baseline: 1.1202x; 1.1202x over previous
#include <cuda_runtime.h>
#include <cstdint>
#include <cstddef>

#define NN 100000
#define EE 1600000
#define HD 128
#define CAP 64

typedef unsigned long long ull;

// ---- scratch (__device__ globals; allocations forbidden) ----
__device__ float g_h[(size_t)NN * HD];           // layer input buffer A
__device__ float g_h2[(size_t)NN * HD];          // layer input buffer B (double-buffer)
__device__ float g_hw[(size_t)NN * HD];          // rare-path GEMM operand
__device__ int   g_cnt[NN];
__device__ int   g_col[(size_t)NN * CAP];
__device__ int   g_spill_cnt;
__device__ int2  g_spill[EE];
// k-major transposed weights (built once per launch)
__device__ __align__(16) float g_WinT[128 * 128];
__device__ __align__(16) float g_WdT[2 * 256 * 128];
__device__ __align__(16) float g_WihT[3 * 128 * 128];
__device__ __align__(16) float g_WhhT[3 * 128 * 128];

__device__ __forceinline__ float sigmoidf_(float x) { return 1.0f / (1.0f + expf(-x)); }
__device__ __forceinline__ float softplusf_(float x) {
    return fmaxf(x, 0.0f) + log1pf(expf(-fabsf(x)));
}

// ---- packed f32x2 helpers (FFMA2 only reachable via PTX) ----
__device__ __forceinline__ ull splat2(float x) {
    ull r; asm("mov.b64 %0, {%1, %1};" : "=l"(r) : "f"(x)); return r;
}
__device__ __forceinline__ ull pack2(float lo, float hi) {
    ull r; asm("mov.b64 %0, {%1, %2};" : "=l"(r) : "f"(lo), "f"(hi)); return r;
}
__device__ __forceinline__ void unpack2(float& lo, float& hi, ull v) {
    asm("mov.b64 {%0, %1}, %2;" : "=f"(lo), "=f"(hi) : "l"(v));
}
__device__ __forceinline__ void fma2(ull& d, ull a, ull b) {
    asm("fma.rn.f32x2 %0, %1, %2, %3;" : "=l"(d) : "l"(a), "l"(b), "l"(d));
}

// ---------------------------------------------------------------------------
// Packed 32-k micro-tile: acc[8 nodes][2 pairs] += A[i0..+7][aofs..+31] * WT
// ---------------------------------------------------------------------------
__device__ __forceinline__ void mma8g(ull acc[8][2], const float* __restrict__ WT,
                                      const float* __restrict__ A, int lda, int aofs,
                                      int i0, int j0) {
#pragma unroll
    for (int k4 = 0; k4 < 8; ++k4) {
        ull w[4][2];
#pragma unroll
        for (int t = 0; t < 4; ++t) {
            const ulonglong2 wv = *reinterpret_cast<const ulonglong2*>(
                WT + (k4 * 4 + t) * 128 + j0);
            w[t][0] = wv.x; w[t][1] = wv.y;
        }
#pragma unroll
        for (int u = 0; u < 8; ++u) {
            const float4 av = *reinterpret_cast<const float4*>(
                A + (size_t)(i0 + u) * lda + aofs + k4 * 4);
            ull s;
            s = splat2(av.x); fma2(acc[u][0], s, w[0][0]); fma2(acc[u][1], s, w[0][1]);
            s = splat2(av.y); fma2(acc[u][0], s, w[1][0]); fma2(acc[u][1], s, w[1][1]);
            s = splat2(av.z); fma2(acc[u][0], s, w[2][0]); fma2(acc[u][1], s, w[2][1]);
            s = splat2(av.w); fma2(acc[u][0], s, w[3][0]); fma2(acc[u][1], s, w[3][1]);
        }
    }
}

// ---------------------------------------------------------------------------
// prep: all weight transposes + cnt/spill zero, one kernel.
// ---------------------------------------------------------------------------
__global__ __launch_bounds__(256) void prep_kernel(const float* __restrict__ W_in,
                                                   const float* __restrict__ Wd,
                                                   const float* __restrict__ Wih,
                                                   const float* __restrict__ Whh) {
    const int idx = blockIdx.x * 256 + threadIdx.x;
    if (idx < 16384) {
        const int j = idx >> 7, k = idx & 127;
        g_WinT[k * 128 + j] = W_in[idx];
    } else if (idx < 81920) {
        const int e = idx - 16384;
        const int l = e >> 15, rem = e & 32767;
        const int j = rem >> 8, k = rem & 255;
        g_WdT[l * 32768 + k * 128 + j] = Wd[e];
    } else if (idx < 131072) {
        const int e = idx - 81920;
        const int j = e >> 7, k = e & 127;
        const int g = j >> 7, jj = j & 127;
        g_WihT[g * 16384 + k * 128 + jj] = Wih[e];
    } else if (idx < 180224) {
        const int e = idx - 131072;
        const int j = e >> 7, k = e & 127;
        const int g = j >> 7, jj = j & 127;
        g_WhhT[g * 16384 + k * 128 + jj] = Whh[e];
    } else if (idx < 280224) {
        g_cnt[idx - 180224] = 0;
    } else if (idx == 280224) {
        g_spill_cnt = 0;
    }
}

// ---------------------------------------------------------------------------
// h0 = relu(x @ W_in^T + b_in)  -> g_h
// ---------------------------------------------------------------------------
__global__ __launch_bounds__(128, 4) void in_gemm_kernel(const float* __restrict__ x,
                                                         const float* __restrict__ b) {
    const int node0 = blockIdx.x * 32;
    const int lane = threadIdx.x & 31;
    const int i0 = (threadIdx.x >> 5) * 8, j0 = lane * 4;
    const float* A = x + (size_t)node0 * HD;

    ull acc[8][2];
    {
        const float4 b4 = *reinterpret_cast<const float4*>(b + j0);
        const ull b0 = pack2(b4.x, b4.y), b1 = pack2(b4.z, b4.w);
#pragma unroll
        for (int u = 0; u < 8; ++u) { acc[u][0] = b0; acc[u][1] = b1; }
    }
#pragma unroll 1
    for (int kt = 0; kt < 4; ++kt)
        mma8g(acc, g_WinT + kt * 4096, A, HD, kt * 32, i0, j0);

#pragma unroll
    for (int u = 0; u < 8; ++u) {
        float a0, a1, a2, a3;
        unpack2(a0, a1, acc[u][0]);
        unpack2(a2, a3, acc[u][1]);
        *reinterpret_cast<float4*>(g_h + (size_t)(node0 + i0 + u) * HD + j0) =
            make_float4(fmaxf(a0, 0.f), fmaxf(a1, 0.f), fmaxf(a2, 0.f), fmaxf(a3, 0.f));
    }
}

// ---------------------------------------------------------------------------
// Edge structure: capacity-slot scatter (exact; overflow -> spill list)
// ---------------------------------------------------------------------------
__global__ __launch_bounds__(256) void scatter_kernel(const int* __restrict__ ei) {
    const int idx = blockIdx.x * 256 + threadIdx.x;  // 2 edges/thread
    const int2 r = reinterpret_cast<const int2*>(ei)[idx];
    const int2 c = reinterpret_cast<const int2*>(ei + EE)[idx];
    int pos = atomicAdd(&g_cnt[r.x], 1);
    if (pos < CAP) g_col[(size_t)r.x * CAP + pos] = c.x;
    else { int s = atomicAdd(&g_spill_cnt, 1); g_spill[s] = make_int2(r.x, c.x); }
    pos = atomicAdd(&g_cnt[r.y], 1);
    if (pos < CAP) g_col[(size_t)r.y * CAP + pos] = c.y;
    else { int s = atomicAdd(&g_spill_cnt, 1); g_spill[s] = make_int2(r.y, c.y); }
}

// ---------------------------------------------------------------------------
// FUSED node kernel, DOUBLE-BUFFERED: reads hin only, writes hout (or out).
// Per-warp gather-aggregate into warp-private smem, then GEMM chain.
// No block syncs; one __syncwarp after gather.
// ---------------------------------------------------------------------------
__global__ __launch_bounds__(128, 4) void node_kernel(
    const float* __restrict__ hin, float* __restrict__ hout,
    int layer, const float* __restrict__ bd,
    const float* __restrict__ Wt, const float* __restrict__ bt,
    const float* __restrict__ bih, const float* __restrict__ bhh,
    const float* __restrict__ Wo, const float* __restrict__ bo,
    float* __restrict__ out, float* __restrict__ tau_out) {
    __shared__ float AGG[32 * 128];   // 16 KB, warp-private strips
    const int node0 = blockIdx.x * 32;
    const int lane = threadIdx.x & 31;
    const int i0 = (threadIdx.x >> 5) * 8, j0 = lane * 4;
    const float* WdTl = g_WdT + layer * 32768;
    const float* Ah = hin + (size_t)node0 * HD;

    // ---- phase 0: gather-aggregate this warp's 8 nodes into AGG ----
#pragma unroll 1
    for (int u = 0; u < 8; ++u) {
        const int node = node0 + i0 + u;
        const float4 hi = *reinterpret_cast<const float4*>(hin + (size_t)node * HD + lane * 4);
        float4 a = make_float4(0.f, 0.f, 0.f, 0.f);
        const int deg = min(g_cnt[node], CAP);
        const int* base = g_col + (size_t)node * CAP;
        int e = 0;
        for (; e + 8 <= deg; e += 8) {
            const int4 ia = *reinterpret_cast<const int4*>(base + e);
            const int4 ib = *reinterpret_cast<const int4*>(base + e + 4);
            const float4 v0 = *reinterpret_cast<const float4*>(hin + (size_t)ia.x * HD + lane * 4);
            const float4 v1 = *reinterpret_cast<const float4*>(hin + (size_t)ia.y * HD + lane * 4);
            const float4 v2 = *reinterpret_cast<const float4*>(hin + (size_t)ia.z * HD + lane * 4);
            const float4 v3 = *reinterpret_cast<const float4*>(hin + (size_t)ia.w * HD + lane * 4);
            const float4 v4 = *reinterpret_cast<const float4*>(hin + (size_t)ib.x * HD + lane * 4);
            const float4 v5 = *reinterpret_cast<const float4*>(hin + (size_t)ib.y * HD + lane * 4);
            const float4 v6 = *reinterpret_cast<const float4*>(hin + (size_t)ib.z * HD + lane * 4);
            const float4 v7 = *reinterpret_cast<const float4*>(hin + (size_t)ib.w * HD + lane * 4);
            a.x += fabsf(hi.x - v0.x) + fabsf(hi.x - v1.x) + fabsf(hi.x - v2.x) + fabsf(hi.x - v3.x)
                 + fabsf(hi.x - v4.x) + fabsf(hi.x - v5.x) + fabsf(hi.x - v6.x) + fabsf(hi.x - v7.x);
            a.y += fabsf(hi.y - v0.y) + fabsf(hi.y - v1.y) + fabsf(hi.y - v2.y) + fabsf(hi.y - v3.y)
                 + fabsf(hi.y - v4.y) + fabsf(hi.y - v5.y) + fabsf(hi.y - v6.y) + fabsf(hi.y - v7.y);
            a.z += fabsf(hi.z - v0.z) + fabsf(hi.z - v1.z) + fabsf(hi.z - v2.z) + fabsf(hi.z - v3.z)
                 + fabsf(hi.z - v4.z) + fabsf(hi.z - v5.z) + fabsf(hi.z - v6.z) + fabsf(hi.z - v7.z);
            a.w += fabsf(hi.w - v0.w) + fabsf(hi.w - v1.w) + fabsf(hi.w - v2.w) + fabsf(hi.w - v3.w)
                 + fabsf(hi.w - v4.w) + fabsf(hi.w - v5.w) + fabsf(hi.w - v6.w) + fabsf(hi.w - v7.w);
        }
        for (; e < deg; ++e) {
            const int c0 = base[e];
            const float4 v = *reinterpret_cast<const float4*>(hin + (size_t)c0 * HD + lane * 4);
            a.x += fabsf(hi.x - v.x);
            a.y += fabsf(hi.y - v.y);
            a.z += fabsf(hi.z - v.z);
            a.w += fabsf(hi.w - v.w);
        }
        *reinterpret_cast<float4*>(AGG + (i0 + u) * 128 + j0) = a;
    }
    // exact spill fix-up (empty unless some node degree > CAP)
    {
        const int sc = g_spill_cnt;
        for (int s = 0; s < sc; ++s) {
            const int2 sp = g_spill[s];
            const int rel = sp.x - (node0 + i0);
            if (rel >= 0 && rel < 8) {
                const float4 aa = *reinterpret_cast<const float4*>(hin + (size_t)sp.x * HD + lane * 4);
                const float4 bb = *reinterpret_cast<const float4*>(hin + (size_t)sp.y * HD + lane * 4);
                float4* p = reinterpret_cast<float4*>(AGG + (i0 + rel) * 128 + j0);
                float4 v = *p;
                v.x += fabsf(aa.x - bb.x); v.y += fabsf(aa.y - bb.y);
                v.z += fabsf(aa.z - bb.z); v.w += fabsf(aa.w - bb.w);
                *p = v;
            }
        }
    }
    __syncwarp();

    // ---- phase 1: hw = relu([h,agg] @ Wd^T + bd) ----
    ull acc[8][2];
    {
        const float4 b4 = *reinterpret_cast<const float4*>(bd + j0);
        const ull b0 = pack2(b4.x, b4.y), b1 = pack2(b4.z, b4.w);
#pragma unroll
        for (int u = 0; u < 8; ++u) { acc[u][0] = b0; acc[u][1] = b1; }
    }
#pragma unroll 1
    for (int kt = 0; kt < 4; ++kt)
        mma8g(acc, WdTl + kt * 4096, Ah, HD, kt * 32, i0, j0);
#pragma unroll 1
    for (int kt = 0; kt < 4; ++kt)
        mma8g(acc, WdTl + 16384 + kt * 4096, AGG, 128, kt * 32, i0, j0);

    float hw[8][4];
#pragma unroll
    for (int u = 0; u < 8; ++u) {
        float a0, a1, a2, a3;
        unpack2(a0, a1, acc[u][0]);
        unpack2(a2, a3, acc[u][1]);
        hw[u][0] = fmaxf(a0, 0.f); hw[u][1] = fmaxf(a1, 0.f);
        hw[u][2] = fmaxf(a2, 0.f); hw[u][3] = fmaxf(a3, 0.f);
    }

    // ---- phase 2: tau (uniform across warp) ----
    const float4 wt4 = *reinterpret_cast<const float4*>(Wt + j0);
    const float bt0 = bt[0];
    int mskbits = 0;
#pragma unroll
    for (int u = 0; u < 8; ++u) {
        float p = hw[u][0] * wt4.x + hw[u][1] * wt4.y +
                  hw[u][2] * wt4.z + hw[u][3] * wt4.w;
#pragma unroll
        for (int o = 16; o > 0; o >>= 1) p += __shfl_xor_sync(0xffffffffu, p, o);
        p = __shfl_sync(0xffffffffu, p, 0);
        const float tv = softplusf_(p + bt0);
        if (tau_out && lane == 0) tau_out[node0 + i0 + u] = tv;
        if (tv < 0.005f) mskbits |= 1 << u;
    }
    const bool rare = __any_sync(0xffffffffu, mskbits != 0);

    if (!rare) {
        if (out) {
            const float4 wo0 = *reinterpret_cast<const float4*>(Wo + j0);
            const float4 wo1 = *reinterpret_cast<const float4*>(Wo + 128 + j0);
            const float bo0 = bo[0], bo1 = bo[1];
#pragma unroll
            for (int u = 0; u < 8; ++u) {
                float p0 = hw[u][0] * wo0.x + hw[u][1] * wo0.y + hw[u][2] * wo0.z + hw[u][3] * wo0.w;
                float p1 = hw[u][0] * wo1.x + hw[u][1] * wo1.y + hw[u][2] * wo1.z + hw[u][3] * wo1.w;
#pragma unroll
                for (int o = 16; o > 0; o >>= 1) {
                    p0 += __shfl_xor_sync(0xffffffffu, p0, o);
                    p1 += __shfl_xor_sync(0xffffffffu, p1, o);
                }
                if (lane == 0)
                    *reinterpret_cast<float2*>(out + (size_t)(node0 + i0 + u) * 2) =
                        make_float2(p0 + bo0, p1 + bo1);
            }
        } else {
#pragma unroll
            for (int u = 0; u < 8; ++u)
                *reinterpret_cast<float4*>(hout + (size_t)(node0 + i0 + u) * HD + j0) =
                    make_float4(hw[u][0], hw[u][1], hw[u][2], hw[u][3]);
        }
        return;
    }

    // ---- rare path: exact per-warp masked GRU(agg, hw) ----
    const float* Ahw = g_hw + (size_t)node0 * HD;
#pragma unroll
    for (int u = 0; u < 8; ++u)
        *reinterpret_cast<float4*>(g_hw + (size_t)(node0 + i0 + u) * HD + j0) =
            make_float4(hw[u][0], hw[u][1], hw[u][2], hw[u][3]);
    __threadfence_block();
    __syncwarp();

    // r gate
    float r_[8][4];
    {
        ull ga[8][2];
        const float4 bi = *reinterpret_cast<const float4*>(bih + j0);
        const float4 bh = *reinterpret_cast<const float4*>(bhh + j0);
        const ull b0 = pack2(bi.x + bh.x, bi.y + bh.y);
        const ull b1 = pack2(bi.z + bh.z, bi.w + bh.w);
#pragma unroll
        for (int u = 0; u < 8; ++u) { ga[u][0] = b0; ga[u][1] = b1; }
#pragma unroll 1
        for (int kt = 0; kt < 4; ++kt)
            mma8g(ga, g_WihT + kt * 4096, AGG, 128, kt * 32, i0, j0);
#pragma unroll 1
        for (int kt = 0; kt < 4; ++kt)
            mma8g(ga, g_WhhT + kt * 4096, Ahw, HD, kt * 32, i0, j0);
#pragma unroll
        for (int u = 0; u < 8; ++u) {
            float a0, a1, a2, a3;
            unpack2(a0, a1, ga[u][0]); unpack2(a2, a3, ga[u][1]);
            r_[u][0] = sigmoidf_(a0); r_[u][1] = sigmoidf_(a1);
            r_[u][2] = sigmoidf_(a2); r_[u][3] = sigmoidf_(a3);
        }
    }
    // rh = r * (bhh_n + hw@Whhn^T)
    float rh[8][4];
    {
        ull hn[8][2];
        const float4 bh = *reinterpret_cast<const float4*>(bhh + 256 + j0);
        const ull b0 = pack2(bh.x, bh.y), b1 = pack2(bh.z, bh.w);
#pragma unroll
        for (int u = 0; u < 8; ++u) { hn[u][0] = b0; hn[u][1] = b1; }
#pragma unroll 1
        for (int kt = 0; kt < 4; ++kt)
            mma8g(hn, g_WhhT + 32768 + kt * 4096, Ahw, HD, kt * 32, i0, j0);
#pragma unroll
        for (int u = 0; u < 8; ++u) {
            float a0, a1, a2, a3;
            unpack2(a0, a1, hn[u][0]); unpack2(a2, a3, hn[u][1]);
            rh[u][0] = r_[u][0] * a0; rh[u][1] = r_[u][1] * a1;
            rh[u][2] = r_[u][2] * a2; rh[u][3] = r_[u][3] * a3;
        }
    }
    // n = tanh(bih_n + agg@Wihn^T + rh)
    float n_[8][4];
    {
        ull in_[8][2];
        const float4 bi = *reinterpret_cast<const float4*>(bih + 256 + j0);
        const ull b0 = pack2(bi.x, bi.y), b1 = pack2(bi.z, bi.w);
#pragma unroll
        for (int u = 0; u < 8; ++u) { in_[u][0] = b0; in_[u][1] = b1; }
#pragma unroll 1
        for (int kt = 0; kt < 4; ++kt)
            mma8g(in_, g_WihT + 32768 + kt * 4096, AGG, 128, kt * 32, i0, j0);
#pragma unroll
        for (int u = 0; u < 8; ++u) {
            float a0, a1, a2, a3;
            unpack2(a0, a1, in_[u][0]); unpack2(a2, a3, in_[u][1]);
            n_[u][0] = tanhf(a0 + rh[u][0]); n_[u][1] = tanhf(a1 + rh[u][1]);
            n_[u][2] = tanhf(a2 + rh[u][2]); n_[u][3] = tanhf(a3 + rh[u][3]);
        }
    }
    // z gate + combine + output
    {
        ull gz[8][2];
        const float4 bi = *reinterpret_cast<const float4*>(bih + 128 + j0);
        const float4 bh = *reinterpret_cast<const float4*>(bhh + 128 + j0);
        const ull b0 = pack2(bi.x + bh.x, bi.y + bh.y);
        const ull b1 = pack2(bi.z + bh.z, bi.w + bh.w);
#pragma unroll
        for (int u = 0; u < 8; ++u) { gz[u][0] = b0; gz[u][1] = b1; }
#pragma unroll 1
        for (int kt = 0; kt < 4; ++kt)
            mma8g(gz, g_WihT + 16384 + kt * 4096, AGG, 128, kt * 32, i0, j0);
#pragma unroll 1
        for (int kt = 0; kt < 4; ++kt)
            mma8g(gz, g_WhhT + 16384 + kt * 4096, Ahw, HD, kt * 32, i0, j0);

        const float4 wo0 = out ? *reinterpret_cast<const float4*>(Wo + j0) : make_float4(0,0,0,0);
        const float4 wo1 = out ? *reinterpret_cast<const float4*>(Wo + 128 + j0) : make_float4(0,0,0,0);
        const float bo0 = out ? bo[0] : 0.f, bo1 = out ? bo[1] : 0.f;
#pragma unroll
        for (int u = 0; u < 8; ++u) {
            float a0, a1, a2, a3;
            unpack2(a0, a1, gz[u][0]); unpack2(a2, a3, gz[u][1]);
            const float zv[4] = {sigmoidf_(a0), sigmoidf_(a1), sigmoidf_(a2), sigmoidf_(a3)};
            const bool msk = (mskbits >> u) & 1;
            float ov[4];
#pragma unroll
            for (int v = 0; v < 4; ++v) {
                const float hn = (1.0f - zv[v]) * n_[u][v] + zv[v] * hw[u][v];
                ov[v] = msk ? hn : hw[u][v];
            }
            if (out) {
                float p0 = ov[0] * wo0.x + ov[1] * wo0.y + ov[2] * wo0.z + ov[3] * wo0.w;
                float p1 = ov[0] * wo1.x + ov[1] * wo1.y + ov[2] * wo1.z + ov[3] * wo1.w;
#pragma unroll
                for (int o = 16; o > 0; o >>= 1) {
                    p0 += __shfl_xor_sync(0xffffffffu, p0, o);
                    p1 += __shfl_xor_sync(0xffffffffu, p1, o);
                }
                if (lane == 0)
                    *reinterpret_cast<float2*>(out + (size_t)(node0 + i0 + u) * 2) =
                        make_float2(p0 + bo0, p1 + bo1);
            } else {
                *reinterpret_cast<float4*>(hout + (size_t)(node0 + i0 + u) * HD + j0) =
                    make_float4(ov[0], ov[1], ov[2], ov[3]);
            }
        }
    }
}

// ---------------------------------------------------------------------------
extern "C" void kernel_launch(void* const* d_in, const int* in_sizes, int n_in,
                              void* d_out, int out_size) {
    const float* x    = (const float*)d_in[0];
    const int*   ei   = (const int*)d_in[1];   // int32 (JAX x64-disabled)
    const float* W_in = (const float*)d_in[2];
    const float* b_in = (const float*)d_in[3];
    const float* Wd   = (const float*)d_in[4];
    const float* bd   = (const float*)d_in[5];
    const float* Wt   = (const float*)d_in[6];
    const float* bt   = (const float*)d_in[7];
    const float* Wih  = (const float*)d_in[8];
    const float* Whh  = (const float*)d_in[9];
    const float* bih  = (const float*)d_in[10];
    const float* bhh  = (const float*)d_in[11];
    const float* Wo   = (const float*)d_in[12];
    const float* bo   = (const float*)d_in[13];

    float* out = (float*)d_out;
    float* tau_out = (out_size >= NN * 3) ? out + (size_t)NN * 2 : nullptr;

    float *hA, *hB;
    cudaGetSymbolAddress((void**)&hA, g_h);
    cudaGetSymbolAddress((void**)&hB, g_h2);

    prep_kernel<<<(280225 + 255) / 256, 256>>>(W_in, Wd, Wih, Whh);
    scatter_kernel<<<EE / 512, 256>>>(ei);
    in_gemm_kernel<<<NN / 32, 128>>>(x, b_in);   // -> g_h (hA)

    // layer 0: read hA, write hB   |   layer 1: read hB, write out
    node_kernel<<<NN / 32, 128>>>(hA, hB, 0, bd, Wt, bt, bih, bhh,
                                  Wo, bo, nullptr, nullptr);
    node_kernel<<<NN / 32, 128>>>(hB, nullptr, 1, bd + HD, Wt, bt, bih, bhh,
                                  Wo, bo, out, tau_out);
}